// round 3
// baseline (speedup 1.0000x reference)
#include <cuda_runtime.h>
#include <math.h>

#define NC   256
#define HW   16384
#define NP   320
#define TAUF 20.0f
#define EPSF 1e-4f

// Scratch (device globals — no allocation allowed)
__device__ float g_protos[NP * NC];   // pooled protos [p][c]
__device__ float g_pnT[NC * NP];      // normalized protos transposed [c][p]
__device__ float g_qinv[HW];          // per-pixel 1/||q - qbar||

// ---------------------------------------------------------------------------
// Kernel A: 16x16 average pool of sup_x -> protos_raw[p][c], p = s*64+gy*8+gx
// grid (8 gy, 256 c, 5 s), block 128 (one thread per column)
// ---------------------------------------------------------------------------
__global__ void pool_kernel(const float* __restrict__ sup)
{
    int gy = blockIdx.x, c = blockIdx.y, s = blockIdx.z;
    const float* base = sup + ((size_t)(s * NC + c) * 128 + gy * 16) * 128;
    int t = threadIdx.x;           // column 0..127
    float acc = 0.f;
#pragma unroll
    for (int r = 0; r < 16; r++)
        acc += base[r * 128 + t];
    // reduce 16 consecutive lanes (one grid cell each)
#pragma unroll
    for (int o = 8; o; o >>= 1)
        acc += __shfl_down_sync(0xffffffffu, acc, o, 16);
    if ((t & 15) == 0) {
        int gx = t >> 4;
        g_protos[(s * 64 + gy * 8 + gx) * NC + c] = acc * (1.0f / 256.0f);
    }
}

// ---------------------------------------------------------------------------
// Kernel B: center over channels + L2-normalize, store transposed [c][p]
// grid 320, block 256
// ---------------------------------------------------------------------------
__global__ void proto_norm_kernel()
{
    __shared__ float red[8];
    int p = blockIdx.x, c = threadIdx.x;
    float v = g_protos[p * NC + c];

    float t = v;
#pragma unroll
    for (int o = 16; o; o >>= 1) t += __shfl_xor_sync(0xffffffffu, t, o);
    if ((c & 31) == 0) red[c >> 5] = t;
    __syncthreads();
    float tot = 0.f;
#pragma unroll
    for (int i = 0; i < 8; i++) tot += red[i];
    float mean = tot * (1.0f / 256.0f);
    float ctr = v - mean;
    __syncthreads();

    t = ctr * ctr;
#pragma unroll
    for (int o = 16; o; o >>= 1) t += __shfl_xor_sync(0xffffffffu, t, o);
    if ((c & 31) == 0) red[c >> 5] = t;
    __syncthreads();
    tot = 0.f;
#pragma unroll
    for (int i = 0; i < 8; i++) tot += red[i];

    float inv = 1.0f / fmaxf(sqrtf(tot), EPSF);
    g_pnT[c * NP + p] = ctr * inv;
}

// ---------------------------------------------------------------------------
// Kernel C: per-pixel query stats: qinv = 1/max(||q - mean||, EPS)
// grid 64, block 256 (one thread per pixel, loop channels -> coalesced)
// ---------------------------------------------------------------------------
__global__ void qstat_kernel(const float* __restrict__ qry)
{
    int m = blockIdx.x * blockDim.x + threadIdx.x;
    float s = 0.f, ss = 0.f;
#pragma unroll 8
    for (int c = 0; c < NC; c++) {
        float v = qry[c * HW + m];
        s += v; ss += v * v;
    }
    float var = ss - s * s * (1.0f / 256.0f);
    g_qinv[m] = 1.0f / fmaxf(sqrtf(fmaxf(var, 0.f)), EPSF);
}

// ---------------------------------------------------------------------------
// Kernel D: fused GEMM (64 pixels x 320 protos x 256 ch) + softmax/argmax +
//           expected value. 256 threads = 16(nx: proto groups) x 16(my: pixel
//           groups); thread tile = 4 pixels x 20 protos.
// Note: pro_n is exactly zero-mean over channels, so raw qry works; apply
//       qinv * TAU at the end.
// ---------------------------------------------------------------------------
__global__ __launch_bounds__(256) void main_kernel(const float* __restrict__ qry,
                                                   float* __restrict__ out)
{
    __shared__ __align__(16) float sQ[8][64];
    __shared__ __align__(16) float sP[8][320];

    int tid = threadIdx.x;
    int m0  = blockIdx.x * 64;
    int nx  = tid & 15;     // proto group: protos [nx*20, nx*20+20)
    int my  = tid >> 4;     // pixel group: pixels [my*4, my*4+4)

    float acc[4][20];
#pragma unroll
    for (int i = 0; i < 4; i++)
#pragma unroll
        for (int j = 0; j < 20; j++) acc[i][j] = 0.f;

    for (int kb = 0; kb < NC; kb += 8) {
        // stage Q chunk: 8 x 64 (coalesced: 64-consecutive pixels)
#pragma unroll
        for (int i = 0; i < 2; i++) {
            int idx = tid + i * 256;
            sQ[idx >> 6][idx & 63] = qry[(kb + (idx >> 6)) * HW + m0 + (idx & 63)];
        }
        // stage P chunk: 8 x 320 (coalesced: 320-consecutive protos per row)
#pragma unroll
        for (int i = 0; i < 10; i++) {
            int idx = tid + i * 256;
            int k = idx / 320, pp = idx - k * 320;
            sP[k][pp] = g_pnT[(kb + k) * NP + pp];
        }
        __syncthreads();

#pragma unroll
        for (int k = 0; k < 8; k++) {
            float4 a = *(const float4*)&sQ[k][my * 4];
            float b[20];
#pragma unroll
            for (int j = 0; j < 5; j++) {
                float4 t4 = *(const float4*)&sP[k][nx * 20 + j * 4];
                b[j * 4 + 0] = t4.x; b[j * 4 + 1] = t4.y;
                b[j * 4 + 2] = t4.z; b[j * 4 + 3] = t4.w;
            }
#pragma unroll
            for (int j = 0; j < 20; j++) {
                acc[0][j] += a.x * b[j];
                acc[1][j] += a.y * b[j];
                acc[2][j] += a.z * b[j];
                acc[3][j] += a.w * b[j];
            }
        }
        __syncthreads();
    }

    // Epilogue: per pixel — scale, softmax-weighted mean (== pred_grid), argmax.
#pragma unroll
    for (int ii = 0; ii < 4; ii++) {
        int m = m0 + my * 4 + ii;
        float sc = g_qinv[m] * TAUF;

        float d[20];
        float vmax = -1e30f; int vidx = 0;
#pragma unroll
        for (int j = 0; j < 20; j++) {
            d[j] = acc[ii][j] * sc;
            if (d[j] > vmax) { vmax = d[j]; vidx = nx * 20 + j; }
        }
        // reduce (max, first-index) over the 16 lanes holding this pixel
#pragma unroll
        for (int o = 8; o; o >>= 1) {
            float om = __shfl_xor_sync(0xffffffffu, vmax, o, 16);
            int   oi = __shfl_xor_sync(0xffffffffu, vidx, o, 16);
            if (om > vmax || (om == vmax && oi < vidx)) { vmax = om; vidx = oi; }
        }
        float se = 0.f, sn = 0.f;
#pragma unroll
        for (int j = 0; j < 20; j++) {
            float e = __expf(d[j] - vmax);
            se += e; sn += e * d[j];
        }
#pragma unroll
        for (int o = 8; o; o >>= 1) {
            se += __shfl_xor_sync(0xffffffffu, se, o, 16);
            sn += __shfl_xor_sync(0xffffffffu, sn, o, 16);
        }
        if (nx == 0) {
            out[m]      = sn / se;        // pred_grid
            out[HW + m] = (float)vidx;    // debug_assign
        }
    }
}

// ---------------------------------------------------------------------------
extern "C" void kernel_launch(void* const* d_in, const int* in_sizes, int n_in,
                              void* d_out, int out_size)
{
    const float* qry = (const float*)d_in[0];   // (1,1,256,128,128)
    const float* sup = (const float*)d_in[1];   // (1,5,1,256,128,128)
    // d_in[2] (sup_y) and d_in[3] (thresh) are dead in the reference.
    float* out = (float*)d_out;                 // [pred_grid | debug_assign]

    pool_kernel<<<dim3(8, 256, 5), 128>>>(sup);
    proto_norm_kernel<<<320, 256>>>();
    qstat_kernel<<<64, 256>>>(qry);
    main_kernel<<<256, 256>>>(qry, out);
}

// round 9
// speedup vs baseline: 1.2299x; 1.2299x over previous
#include <cuda_runtime.h>
#include <math.h>

#define NC   256
#define HW   16384
#define NP   320
#define TAUF 20.0f
#define EPSF 1e-4f
#define KB   16

// Scratch (device globals — no allocation allowed)
__device__ float g_protos[NP * NC];   // pooled protos [p][c]
__device__ float g_pnT[NC * NP];      // normalized protos transposed [c][p]
__device__ float g_qinv[HW];          // per-pixel 1/||q - qbar||

// ---------------------------------------------------------------------------
// Kernel A: 16x16 average pool of sup_x -> protos_raw[p][c], p = s*64+gy*8+gx
// grid (8 gy, 256 c, 5 s), block 128 (one thread per column)
// ---------------------------------------------------------------------------
__global__ void pool_kernel(const float* __restrict__ sup)
{
    int gy = blockIdx.x, c = blockIdx.y, s = blockIdx.z;
    const float* base = sup + ((size_t)(s * NC + c) * 128 + gy * 16) * 128;
    int t = threadIdx.x;           // column 0..127
    float acc = 0.f;
#pragma unroll
    for (int r = 0; r < 16; r++)
        acc += base[r * 128 + t];
    // reduce 16 consecutive lanes (one grid cell each)
#pragma unroll
    for (int o = 8; o; o >>= 1)
        acc += __shfl_down_sync(0xffffffffu, acc, o, 16);
    if ((t & 15) == 0) {
        int gx = t >> 4;
        g_protos[(s * 64 + gy * 8 + gx) * NC + c] = acc * (1.0f / 256.0f);
    }
}

// ---------------------------------------------------------------------------
// Kernel B: center over channels + L2-normalize, store transposed [c][p]
// grid 320, block 256
// ---------------------------------------------------------------------------
__global__ void proto_norm_kernel()
{
    __shared__ float red[8];
    int p = blockIdx.x, c = threadIdx.x;
    float v = g_protos[p * NC + c];

    float t = v;
#pragma unroll
    for (int o = 16; o; o >>= 1) t += __shfl_xor_sync(0xffffffffu, t, o);
    if ((c & 31) == 0) red[c >> 5] = t;
    __syncthreads();
    float tot = 0.f;
#pragma unroll
    for (int i = 0; i < 8; i++) tot += red[i];
    float mean = tot * (1.0f / 256.0f);
    float ctr = v - mean;
    __syncthreads();

    t = ctr * ctr;
#pragma unroll
    for (int o = 16; o; o >>= 1) t += __shfl_xor_sync(0xffffffffu, t, o);
    if ((c & 31) == 0) red[c >> 5] = t;
    __syncthreads();
    tot = 0.f;
#pragma unroll
    for (int i = 0; i < 8; i++) tot += red[i];

    float inv = 1.0f / fmaxf(sqrtf(tot), EPSF);
    g_pnT[c * NP + p] = ctr * inv;
}

// ---------------------------------------------------------------------------
// Kernel C: per-pixel query stats: qinv = 1/max(||q - mean||, EPS)
// grid 64, block 256 (one thread per pixel, loop channels -> coalesced)
// ---------------------------------------------------------------------------
__global__ void qstat_kernel(const float* __restrict__ qry)
{
    int m = blockIdx.x * blockDim.x + threadIdx.x;
    float s = 0.f, ss = 0.f;
#pragma unroll 8
    for (int c = 0; c < NC; c++) {
        float v = qry[c * HW + m];
        s += v; ss += v * v;
    }
    float var = ss - s * s * (1.0f / 256.0f);
    g_qinv[m] = 1.0f / fmaxf(sqrtf(fmaxf(var, 0.f)), EPSF);
}

// ---------------------------------------------------------------------------
// Kernel D: fused GEMM (64 pixels x 320 protos x 256 ch) + softmax/argmax +
//           expected value. 256 threads = 16(nx) x 16(my); thread tile =
//           4 pixels x 20 protos, protos INTERLEAVED: lane nx owns
//           {nx*4 + 64*j4 + jj : j4<5, jj<4} -> conflict-free LDS.128
//           (inter-lane stride 16B vs 80B before).
// __launch_bounds__(256,2): cap regs at 128 so TWO blocks co-reside per SM
// (16 warps). grid=256 <= 148*2 slots -> single wave, no tail.
// pro_n is exactly zero-mean over channels, so raw qry works; apply
// qinv * TAU at the end.
// ---------------------------------------------------------------------------
__global__ __launch_bounds__(256, 2) void main_kernel(const float* __restrict__ qry,
                                                      float* __restrict__ out)
{
    __shared__ __align__(16) float sQ[KB][64];    // 4 KB
    __shared__ __align__(16) float sP[KB][320];   // 20 KB

    int tid = threadIdx.x;
    int m0  = blockIdx.x * 64;
    int nx  = tid & 15;     // proto group (interleaved)
    int my  = tid >> 4;     // pixel group: pixels [my*4, my*4+4)

    float acc[4][20];
#pragma unroll
    for (int i = 0; i < 4; i++)
#pragma unroll
        for (int j = 0; j < 20; j++) acc[i][j] = 0.f;

    for (int kb = 0; kb < NC; kb += KB) {
        // stage Q chunk: 16 x 64 floats = 256 float4 (one per thread)
        {
            int row = tid >> 4, col = (tid & 15) * 4;
            *(float4*)&sQ[row][col] =
                *(const float4*)&qry[(size_t)(kb + row) * HW + m0 + col];
        }
        // stage P chunk: 16 x 320 floats = 1280 float4 (5 per thread)
#pragma unroll
        for (int i = 0; i < 5; i++) {
            int idx4 = tid + i * 256;          // float4 index
            int k  = idx4 / 80;                // 80 float4 per row
            int pp = (idx4 - k * 80) * 4;
            *(float4*)&sP[k][pp] =
                *(const float4*)&g_pnT[(size_t)(kb + k) * NP + pp];
        }
        __syncthreads();

#pragma unroll
        for (int k = 0; k < KB; k++) {
            float4 a = *(const float4*)&sQ[k][my * 4];
            float b[20];
#pragma unroll
            for (int j4 = 0; j4 < 5; j4++) {
                float4 t4 = *(const float4*)&sP[k][nx * 4 + j4 * 64];
                b[j4 * 4 + 0] = t4.x; b[j4 * 4 + 1] = t4.y;
                b[j4 * 4 + 2] = t4.z; b[j4 * 4 + 3] = t4.w;
            }
#pragma unroll
            for (int j = 0; j < 20; j++) {
                acc[0][j] += a.x * b[j];
                acc[1][j] += a.y * b[j];
                acc[2][j] += a.z * b[j];
                acc[3][j] += a.w * b[j];
            }
        }
        __syncthreads();
    }

    // Epilogue: per pixel — scale, softmax-weighted mean (== pred_grid), argmax.
    // Lane nx's j-th value corresponds to proto index nx*4 + (j>>2)*64 + (j&3),
    // which is ascending in j, so strict '>' keeps the smallest index per lane.
#pragma unroll
    for (int ii = 0; ii < 4; ii++) {
        int m = m0 + my * 4 + ii;
        float sc = g_qinv[m] * TAUF;

        float d[20];
        float vmax = -1e30f; int vidx = 0;
#pragma unroll
        for (int j = 0; j < 20; j++) {
            d[j] = acc[ii][j] * sc;
            int pidx = nx * 4 + (j >> 2) * 64 + (j & 3);
            if (d[j] > vmax) { vmax = d[j]; vidx = pidx; }
        }
        // reduce (max, first-index) over the 16 lanes holding this pixel
#pragma unroll
        for (int o = 8; o; o >>= 1) {
            float om = __shfl_xor_sync(0xffffffffu, vmax, o, 16);
            int   oi = __shfl_xor_sync(0xffffffffu, vidx, o, 16);
            if (om > vmax || (om == vmax && oi < vidx)) { vmax = om; vidx = oi; }
        }
        float se = 0.f, sn = 0.f;
#pragma unroll
        for (int j = 0; j < 20; j++) {
            float e = __expf(d[j] - vmax);
            se += e; sn += e * d[j];
        }
#pragma unroll
        for (int o = 8; o; o >>= 1) {
            se += __shfl_xor_sync(0xffffffffu, se, o, 16);
            sn += __shfl_xor_sync(0xffffffffu, sn, o, 16);
        }
        if (nx == 0) {
            out[m]      = sn / se;        // pred_grid
            out[HW + m] = (float)vidx;    // debug_assign
        }
    }
}

// ---------------------------------------------------------------------------
extern "C" void kernel_launch(void* const* d_in, const int* in_sizes, int n_in,
                              void* d_out, int out_size)
{
    const float* qry = (const float*)d_in[0];   // (1,1,256,128,128)
    const float* sup = (const float*)d_in[1];   // (1,5,1,256,128,128)
    // d_in[2] (sup_y) and d_in[3] (thresh) are dead in the reference.
    float* out = (float*)d_out;                 // [pred_grid | debug_assign]

    pool_kernel<<<dim3(8, 256, 5), 128>>>(sup);
    qstat_kernel<<<64, 256>>>(qry);
    proto_norm_kernel<<<320, 256>>>();
    main_kernel<<<256, 256>>>(qry, out);
}

// round 10
// speedup vs baseline: 1.3030x; 1.0594x over previous
#include <cuda_runtime.h>
#include <math.h>

#define NC   256
#define HW   16384
#define NP   320
#define TAUF 20.0f
#define EPSF 1e-4f
#define KB   16

// Scratch (device globals — no allocation allowed)
__device__ float g_protos[NP * NC];   // pooled protos [p][c]
__device__ float g_pnT[NC * NP];      // normalized protos transposed [c][p]
__device__ float g_qinv[HW];          // per-pixel 1/||q - qbar||

// ---------------------------------------------------------------------------
// Kernel A: 16x16 average pool of sup_x -> protos_raw[p][c], p = s*64+gy*8+gx
// grid (8 gy, 256 c, 5 s), block 128 (one thread per column)
// ---------------------------------------------------------------------------
__global__ void pool_kernel(const float* __restrict__ sup)
{
    int gy = blockIdx.x, c = blockIdx.y, s = blockIdx.z;
    const float* base = sup + ((size_t)(s * NC + c) * 128 + gy * 16) * 128;
    int t = threadIdx.x;           // column 0..127
    float acc = 0.f;
#pragma unroll
    for (int r = 0; r < 16; r++)
        acc += base[r * 128 + t];
    // reduce 16 consecutive lanes (one grid cell each)
#pragma unroll
    for (int o = 8; o; o >>= 1)
        acc += __shfl_down_sync(0xffffffffu, acc, o, 16);
    if ((t & 15) == 0) {
        int gx = t >> 4;
        g_protos[(s * 64 + gy * 8 + gx) * NC + c] = acc * (1.0f / 256.0f);
    }
}

// ---------------------------------------------------------------------------
// Kernel B: center over channels + L2-normalize, store transposed [c][p]
// grid 320, block 256
// ---------------------------------------------------------------------------
__global__ void proto_norm_kernel()
{
    __shared__ float red[8];
    int p = blockIdx.x, c = threadIdx.x;
    float v = g_protos[p * NC + c];

    float t = v;
#pragma unroll
    for (int o = 16; o; o >>= 1) t += __shfl_xor_sync(0xffffffffu, t, o);
    if ((c & 31) == 0) red[c >> 5] = t;
    __syncthreads();
    float tot = 0.f;
#pragma unroll
    for (int i = 0; i < 8; i++) tot += red[i];
    float mean = tot * (1.0f / 256.0f);
    float ctr = v - mean;
    __syncthreads();

    t = ctr * ctr;
#pragma unroll
    for (int o = 16; o; o >>= 1) t += __shfl_xor_sync(0xffffffffu, t, o);
    if ((c & 31) == 0) red[c >> 5] = t;
    __syncthreads();
    tot = 0.f;
#pragma unroll
    for (int i = 0; i < 8; i++) tot += red[i];

    float inv = 1.0f / fmaxf(sqrtf(tot), EPSF);
    g_pnT[c * NP + p] = ctr * inv;
}

// ---------------------------------------------------------------------------
// Kernel C: per-pixel query stats: qinv = 1/max(||q - mean||, EPS)
// grid 64, block 256 (one thread per pixel, loop channels -> coalesced)
// ---------------------------------------------------------------------------
__global__ void qstat_kernel(const float* __restrict__ qry)
{
    int m = blockIdx.x * blockDim.x + threadIdx.x;
    float s = 0.f, ss = 0.f;
#pragma unroll 8
    for (int c = 0; c < NC; c++) {
        float v = qry[c * HW + m];
        s += v; ss += v * v;
    }
    float var = ss - s * s * (1.0f / 256.0f);
    g_qinv[m] = 1.0f / fmaxf(sqrtf(fmaxf(var, 0.f)), EPSF);
}

// ---------------------------------------------------------------------------
// Kernel D: fused GEMM (64 pixels x 320 protos x 256 ch) + softmax/argmax +
//           expected value, with PACKED f32x2 FMAs (SASS FFMA2) to reach the
//           128-FMA/cyc/SM fp32 peak (scalar FFMA caps at 64/cyc/SM — round-9
//           kernel measured exactly at that roof).
// Thread tile: 4 pixels x 10 PROTO-PAIRS (20 protos). Proto pairs come packed
// for free from the LDS.128 of sP (ulonglong2 aliasing); pixel values are
// broadcast-packed with one mov.b64 {a,a} each.
// Proto interleave: lane nx owns protos {nx*4 + 64*j4 + jj} -> conflict-free
// LDS.128 (16-lane stride 16B). Packed lanes = consecutive proto indices.
// __launch_bounds__(256,2): 2 blocks/SM (16 warps), grid 256 <= 296 slots.
// pro_n is exactly zero-mean over channels, so raw qry works; apply
// qinv * TAU at the end.
// ---------------------------------------------------------------------------
__global__ __launch_bounds__(256, 2) void main_kernel(const float* __restrict__ qry,
                                                      float* __restrict__ out)
{
    __shared__ __align__(16) float sQ[KB][64];    // 4 KB
    __shared__ __align__(16) float sP[KB][320];   // 20 KB

    int tid = threadIdx.x;
    int m0  = blockIdx.x * 64;
    int nx  = tid & 15;     // proto group (interleaved)
    int my  = tid >> 4;     // pixel group: pixels [my*4, my*4+4)

    // acc2[i][j2]: packed (f32,f32) accumulator, pixel i, proto pair j2.
    unsigned long long acc2[4][10];
#pragma unroll
    for (int i = 0; i < 4; i++)
#pragma unroll
        for (int j = 0; j < 10; j++) acc2[i][j] = 0ull;   // (+0.f, +0.f)

    for (int kb = 0; kb < NC; kb += KB) {
        // stage Q chunk: 16 x 64 floats = 256 float4 (one per thread)
        {
            int row = tid >> 4, col = (tid & 15) * 4;
            *(float4*)&sQ[row][col] =
                *(const float4*)&qry[(size_t)(kb + row) * HW + m0 + col];
        }
        // stage P chunk: 16 x 320 floats = 1280 float4 (5 per thread)
#pragma unroll
        for (int i = 0; i < 5; i++) {
            int idx4 = tid + i * 256;          // float4 index
            int k  = idx4 / 80;                // 80 float4 per row
            int pp = (idx4 - k * 80) * 4;
            *(float4*)&sP[k][pp] =
                *(const float4*)&g_pnT[(size_t)(kb + k) * NP + pp];
        }
        __syncthreads();

#pragma unroll
        for (int k = 0; k < KB; k++) {
            float4 a = *(const float4*)&sQ[k][my * 4];
            unsigned long long a0, a1, a2, a3;
            asm("mov.b64 %0, {%1, %1};" : "=l"(a0) : "f"(a.x));
            asm("mov.b64 %0, {%1, %1};" : "=l"(a1) : "f"(a.y));
            asm("mov.b64 %0, {%1, %1};" : "=l"(a2) : "f"(a.z));
            asm("mov.b64 %0, {%1, %1};" : "=l"(a3) : "f"(a.w));
#pragma unroll
            for (int j4 = 0; j4 < 5; j4++) {
                // LDS.128 -> 4 consecutive f32 regs; u64 views = packed pairs
                ulonglong2 b2 = *(const ulonglong2*)&sP[k][nx * 4 + j4 * 64];
                asm("fma.rn.f32x2 %0, %1, %2, %0;" : "+l"(acc2[0][j4*2  ]) : "l"(a0), "l"(b2.x));
                asm("fma.rn.f32x2 %0, %1, %2, %0;" : "+l"(acc2[0][j4*2+1]) : "l"(a0), "l"(b2.y));
                asm("fma.rn.f32x2 %0, %1, %2, %0;" : "+l"(acc2[1][j4*2  ]) : "l"(a1), "l"(b2.x));
                asm("fma.rn.f32x2 %0, %1, %2, %0;" : "+l"(acc2[1][j4*2+1]) : "l"(a1), "l"(b2.y));
                asm("fma.rn.f32x2 %0, %1, %2, %0;" : "+l"(acc2[2][j4*2  ]) : "l"(a2), "l"(b2.x));
                asm("fma.rn.f32x2 %0, %1, %2, %0;" : "+l"(acc2[2][j4*2+1]) : "l"(a2), "l"(b2.y));
                asm("fma.rn.f32x2 %0, %1, %2, %0;" : "+l"(acc2[3][j4*2  ]) : "l"(a3), "l"(b2.x));
                asm("fma.rn.f32x2 %0, %1, %2, %0;" : "+l"(acc2[3][j4*2+1]) : "l"(a3), "l"(b2.y));
            }
        }
        __syncthreads();
    }

    // Epilogue: per pixel — scale, softmax-weighted mean (== pred_grid), argmax.
    // Unpack: pair j2 = j4*2 + h holds protos nx*4 + j4*64 + h*2 + {0,1};
    // d[j] with j = j2*2 + bit gives pidx = nx*4 + (j>>2)*64 + (j&3),
    // ascending in j, so strict '>' keeps the smallest index per lane.
#pragma unroll
    for (int ii = 0; ii < 4; ii++) {
        int m = m0 + my * 4 + ii;
        float sc = g_qinv[m] * TAUF;

        float d[20];
#pragma unroll
        for (int j2 = 0; j2 < 10; j2++) {
            float lo, hi;
            asm("mov.b64 {%0, %1}, %2;" : "=f"(lo), "=f"(hi) : "l"(acc2[ii][j2]));
            d[j2 * 2 + 0] = lo * sc;
            d[j2 * 2 + 1] = hi * sc;
        }
        float vmax = -1e30f; int vidx = 0;
#pragma unroll
        for (int j = 0; j < 20; j++) {
            int pidx = nx * 4 + (j >> 2) * 64 + (j & 3);
            if (d[j] > vmax) { vmax = d[j]; vidx = pidx; }
        }
        // reduce (max, first-index) over the 16 lanes holding this pixel
#pragma unroll
        for (int o = 8; o; o >>= 1) {
            float om = __shfl_xor_sync(0xffffffffu, vmax, o, 16);
            int   oi = __shfl_xor_sync(0xffffffffu, vidx, o, 16);
            if (om > vmax || (om == vmax && oi < vidx)) { vmax = om; vidx = oi; }
        }
        float se = 0.f, sn = 0.f;
#pragma unroll
        for (int j = 0; j < 20; j++) {
            float e = __expf(d[j] - vmax);
            se += e; sn += e * d[j];
        }
#pragma unroll
        for (int o = 8; o; o >>= 1) {
            se += __shfl_xor_sync(0xffffffffu, se, o, 16);
            sn += __shfl_xor_sync(0xffffffffu, sn, o, 16);
        }
        if (nx == 0) {
            out[m]      = sn / se;        // pred_grid
            out[HW + m] = (float)vidx;    // debug_assign
        }
    }
}

// ---------------------------------------------------------------------------
extern "C" void kernel_launch(void* const* d_in, const int* in_sizes, int n_in,
                              void* d_out, int out_size)
{
    const float* qry = (const float*)d_in[0];   // (1,1,256,128,128)
    const float* sup = (const float*)d_in[1];   // (1,5,1,256,128,128)
    // d_in[2] (sup_y) and d_in[3] (thresh) are dead in the reference.
    float* out = (float*)d_out;                 // [pred_grid | debug_assign]

    pool_kernel<<<dim3(8, 256, 5), 128>>>(sup);
    qstat_kernel<<<64, 256>>>(qry);
    proto_norm_kernel<<<320, 256>>>();
    main_kernel<<<256, 256>>>(qry, out);
}

// round 11
// speedup vs baseline: 1.4320x; 1.0990x over previous
#include <cuda_runtime.h>
#include <math.h>

#define NC   256
#define HW   16384
#define NP   320
#define TAUF 20.0f
#define EPSF 1e-4f
#define KB   32

// Scratch (device globals — no allocation allowed)
__device__ float g_protos[NP * NC];   // pooled protos [p][c]
__device__ float g_pnT[NC * NP];      // normalized protos transposed [c][p]

// ---------------------------------------------------------------------------
// Kernel A: 16x16 average pool of sup_x -> protos_raw[p][c], p = s*64+gy*8+gx
// grid (8 gy, 256 c, 5 s), block 128 (one thread per column)
// ---------------------------------------------------------------------------
__global__ void pool_kernel(const float* __restrict__ sup)
{
    int gy = blockIdx.x, c = blockIdx.y, s = blockIdx.z;
    const float* base = sup + ((size_t)(s * NC + c) * 128 + gy * 16) * 128;
    int t = threadIdx.x;           // column 0..127
    float acc = 0.f;
#pragma unroll
    for (int r = 0; r < 16; r++)
        acc += base[r * 128 + t];
#pragma unroll
    for (int o = 8; o; o >>= 1)
        acc += __shfl_down_sync(0xffffffffu, acc, o, 16);
    if ((t & 15) == 0) {
        int gx = t >> 4;
        g_protos[(s * 64 + gy * 8 + gx) * NC + c] = acc * (1.0f / 256.0f);
    }
}

// ---------------------------------------------------------------------------
// Kernel B: center over channels + L2-normalize, store transposed [c][p]
// grid 320, block 256
// ---------------------------------------------------------------------------
__global__ void proto_norm_kernel()
{
    __shared__ float red[8];
    int p = blockIdx.x, c = threadIdx.x;
    float v = g_protos[p * NC + c];

    float t = v;
#pragma unroll
    for (int o = 16; o; o >>= 1) t += __shfl_xor_sync(0xffffffffu, t, o);
    if ((c & 31) == 0) red[c >> 5] = t;
    __syncthreads();
    float tot = 0.f;
#pragma unroll
    for (int i = 0; i < 8; i++) tot += red[i];
    float mean = tot * (1.0f / 256.0f);
    float ctr = v - mean;
    __syncthreads();

    t = ctr * ctr;
#pragma unroll
    for (int o = 16; o; o >>= 1) t += __shfl_xor_sync(0xffffffffu, t, o);
    if ((c & 31) == 0) red[c >> 5] = t;
    __syncthreads();
    tot = 0.f;
#pragma unroll
    for (int i = 0; i < 8; i++) tot += red[i];

    float inv = 1.0f / fmaxf(sqrtf(tot), EPSF);
    g_pnT[c * NP + p] = ctr * inv;
}

// ---------------------------------------------------------------------------
// Kernel D: fused GEMM (64 px x 320 protos x 256 ch) + qstat + softmax/argmax
//           + expected value. Packed f32x2 FMAs; FFMA2s grouped so 4
//           consecutive share the SAME b operand -> ptxas .reuse drops b from
//           the RF-bank distinct set (FFMA2 banking floor rt=3 -> ~2).
// Query stats (qinv) are computed from the SAME staging loads (Q is fully
// streamed through sQ), eliminating the separate qstat kernel.
// KB=32: 8 outer iterations (half the barriers of KB=16).
// Proto interleave: lane nx owns protos {nx*4 + 64*j4 + jj} -> conflict-free
// LDS.128. __launch_bounds__(256,2): 2 blocks/SM, grid 256 in one wave.
// pro_n is exactly zero-mean over channels, so raw qry works.
// ---------------------------------------------------------------------------
__global__ __launch_bounds__(256, 2) void main_kernel(const float* __restrict__ qry,
                                                      float* __restrict__ out)
{
    __shared__ __align__(16) float sQ[KB][64];    // 8 KB
    __shared__ __align__(16) float sP[KB][320];   // 40 KB  (total 48 KB)

    int tid = threadIdx.x;
    int m0  = blockIdx.x * 64;
    int nx  = tid & 15;     // proto group (interleaved)
    int my  = tid >> 4;     // pixel group: pixels [my*4, my*4+4)

    // packed (f32,f32) accumulators: pixel i, proto pair j2
    unsigned long long acc2[4][10];
#pragma unroll
    for (int i = 0; i < 4; i++)
#pragma unroll
        for (int j = 0; j < 10; j++) acc2[i][j] = 0ull;

    // per-thread query stats partials: 4 pixels (this thread's staging slot),
    // 16 channels (rows tid>>4 and tid>>4+16 of each chunk)
    float4 s4  = make_float4(0.f, 0.f, 0.f, 0.f);
    float4 ss4 = make_float4(0.f, 0.f, 0.f, 0.f);

    for (int kb = 0; kb < NC; kb += KB) {
        // stage Q chunk: 32 x 64 floats = 512 float4 (2 per thread) + stats
#pragma unroll
        for (int i = 0; i < 2; i++) {
            int idx4 = tid + i * 256;
            int row = idx4 >> 4, col = (idx4 & 15) * 4;
            float4 v = *(const float4*)&qry[(size_t)(kb + row) * HW + m0 + col];
            *(float4*)&sQ[row][col] = v;
            s4.x += v.x; s4.y += v.y; s4.z += v.z; s4.w += v.w;
            ss4.x += v.x * v.x; ss4.y += v.y * v.y;
            ss4.z += v.z * v.z; ss4.w += v.w * v.w;
        }
        // stage P chunk: 32 x 320 floats = 2560 float4 (10 per thread)
#pragma unroll
        for (int i = 0; i < 10; i++) {
            int idx4 = tid + i * 256;
            int k  = idx4 / 80;
            int pp = (idx4 - k * 80) * 4;
            *(float4*)&sP[k][pp] =
                *(const float4*)&g_pnT[(size_t)(kb + k) * NP + pp];
        }
        __syncthreads();

#pragma unroll 8
        for (int k = 0; k < KB; k++) {
            float4 a = *(const float4*)&sQ[k][my * 4];
            unsigned long long a0, a1, a2, a3;
            asm("mov.b64 %0, {%1, %1};" : "=l"(a0) : "f"(a.x));
            asm("mov.b64 %0, {%1, %1};" : "=l"(a1) : "f"(a.y));
            asm("mov.b64 %0, {%1, %1};" : "=l"(a2) : "f"(a.z));
            asm("mov.b64 %0, {%1, %1};" : "=l"(a3) : "f"(a.w));
#pragma unroll
            for (int j4 = 0; j4 < 5; j4++) {
                ulonglong2 b2 = *(const ulonglong2*)&sP[k][nx * 4 + j4 * 64];
                // group by shared b -> slot-2 .reuse -> lower RF-bank rt
                asm("fma.rn.f32x2 %0, %1, %2, %0;" : "+l"(acc2[0][j4*2  ]) : "l"(a0), "l"(b2.x));
                asm("fma.rn.f32x2 %0, %1, %2, %0;" : "+l"(acc2[1][j4*2  ]) : "l"(a1), "l"(b2.x));
                asm("fma.rn.f32x2 %0, %1, %2, %0;" : "+l"(acc2[2][j4*2  ]) : "l"(a2), "l"(b2.x));
                asm("fma.rn.f32x2 %0, %1, %2, %0;" : "+l"(acc2[3][j4*2  ]) : "l"(a3), "l"(b2.x));
                asm("fma.rn.f32x2 %0, %1, %2, %0;" : "+l"(acc2[0][j4*2+1]) : "l"(a0), "l"(b2.y));
                asm("fma.rn.f32x2 %0, %1, %2, %0;" : "+l"(acc2[1][j4*2+1]) : "l"(a1), "l"(b2.y));
                asm("fma.rn.f32x2 %0, %1, %2, %0;" : "+l"(acc2[2][j4*2+1]) : "l"(a2), "l"(b2.y));
                asm("fma.rn.f32x2 %0, %1, %2, %0;" : "+l"(acc2[3][j4*2+1]) : "l"(a3), "l"(b2.y));
            }
        }
        __syncthreads();
    }

    // ---- query-stat reduction (reuse sP memory; all compute reads done) ----
    float2* pr  = (float2*)&sP[0][0];          // [16 rowg][16 colg][4 px] float2
    float*  sqi = (float*)((char*)pr + 8192);  // 64 floats: qinv*TAU per pixel
    {
        int base = (my * 16 + nx) * 4;
        pr[base + 0] = make_float2(s4.x, ss4.x);
        pr[base + 1] = make_float2(s4.y, ss4.y);
        pr[base + 2] = make_float2(s4.z, ss4.z);
        pr[base + 3] = make_float2(s4.w, ss4.w);
    }
    __syncthreads();
    if (tid < 64) {
        int cg = tid >> 2, j = tid & 3;
        float s = 0.f, ss = 0.f;
#pragma unroll
        for (int r = 0; r < 16; r++) {
            float2 t = pr[(r * 16 + cg) * 4 + j];
            s += t.x; ss += t.y;
        }
        float var = ss - s * s * (1.0f / 256.0f);
        sqi[tid] = TAUF / fmaxf(sqrtf(fmaxf(var, 0.f)), EPSF);
    }
    __syncthreads();

    // ---- epilogue: scale, softmax-weighted mean (== pred_grid), argmax ----
    // pair j2 = j4*2+h holds protos nx*4 + j4*64 + h*2 + {0,1};
    // d[j], j=j2*2+bit -> pidx = nx*4 + (j>>2)*64 + (j&3), ascending in j.
#pragma unroll
    for (int ii = 0; ii < 4; ii++) {
        int m = m0 + my * 4 + ii;
        float sc = sqi[my * 4 + ii];

        float d[20];
#pragma unroll
        for (int j2 = 0; j2 < 10; j2++) {
            float lo, hi;
            asm("mov.b64 {%0, %1}, %2;" : "=f"(lo), "=f"(hi) : "l"(acc2[ii][j2]));
            d[j2 * 2 + 0] = lo * sc;
            d[j2 * 2 + 1] = hi * sc;
        }
        float vmax = -1e30f; int vidx = 0;
#pragma unroll
        for (int j = 0; j < 20; j++) {
            int pidx = nx * 4 + (j >> 2) * 64 + (j & 3);
            if (d[j] > vmax) { vmax = d[j]; vidx = pidx; }
        }
#pragma unroll
        for (int o = 8; o; o >>= 1) {
            float om = __shfl_xor_sync(0xffffffffu, vmax, o, 16);
            int   oi = __shfl_xor_sync(0xffffffffu, vidx, o, 16);
            if (om > vmax || (om == vmax && oi < vidx)) { vmax = om; vidx = oi; }
        }
        float se = 0.f, sn = 0.f;
#pragma unroll
        for (int j = 0; j < 20; j++) {
            float e = __expf(d[j] - vmax);
            se += e; sn += e * d[j];
        }
#pragma unroll
        for (int o = 8; o; o >>= 1) {
            se += __shfl_xor_sync(0xffffffffu, se, o, 16);
            sn += __shfl_xor_sync(0xffffffffu, sn, o, 16);
        }
        if (nx == 0) {
            out[m]      = sn / se;        // pred_grid
            out[HW + m] = (float)vidx;    // debug_assign
        }
    }
}

// ---------------------------------------------------------------------------
extern "C" void kernel_launch(void* const* d_in, const int* in_sizes, int n_in,
                              void* d_out, int out_size)
{
    const float* qry = (const float*)d_in[0];   // (1,1,256,128,128)
    const float* sup = (const float*)d_in[1];   // (1,5,1,256,128,128)
    // d_in[2] (sup_y) and d_in[3] (thresh) are dead in the reference.
    float* out = (float*)d_out;                 // [pred_grid | debug_assign]

    pool_kernel<<<dim3(8, 256, 5), 128>>>(sup);
    proto_norm_kernel<<<320, 256>>>();
    main_kernel<<<256, 256>>>(qry, out);
}